// round 1
// baseline (speedup 1.0000x reference)
#include <cuda_runtime.h>

#define HH 224
#define WW 224
#define NCH 64
#define BB 4

#define TH 32
#define TW 32
#define FR 47            // TH + 15 halo rows
#define FC 47            // TW + 15 halo cols
#define ROWSTR 392       // 49 * 8 floats per row (pad -> conflict-free scans)
#define SMEM_BYTES (3 * FR * ROWSTR * 4)

// ---------------- device globals (scratch; no allocation) ----------------
__device__ unsigned g_minkey[BB];
__device__ unsigned g_maxkey[BB];
__device__ float    g_sA[BB];      // 1/(max-min+eps)
__device__ float    g_xmin[BB];
__device__ float    g_coef[4];     // OLS coefficients c_s
__device__ float    g_bnS[NCH];    // folded BN scale
__device__ float    g_bnT[NCH];    // folded BN bias

__device__ __forceinline__ unsigned f2key(float f) {
    unsigned u = __float_as_uint(f);
    return (u & 0x80000000u) ? ~u : (u | 0x80000000u);
}
__device__ __forceinline__ float key2f(unsigned k) {
    unsigned u = (k & 0x80000000u) ? (k & 0x7FFFFFFFu) : ~k;
    return __uint_as_float(u);
}

// ---------------- kernel 0: reset atomic scratch ----------------
__global__ void initK() {
    int t = threadIdx.x;
    if (t < BB) { g_minkey[t] = 0xFFFFFFFFu; g_maxkey[t] = 0u; }
}

// ---------------- kernel 1: per-sample min/max ----------------
__global__ void minmaxK(const float* __restrict__ x) {
    const int b = blockIdx.y;
    const int n4 = HH * WW * NCH / 4;
    const float4* xv = reinterpret_cast<const float4*>(x) + (size_t)b * n4;

    float mn = 3.402823466e38f, mx = -3.402823466e38f;
    for (int i = blockIdx.x * blockDim.x + threadIdx.x; i < n4; i += gridDim.x * blockDim.x) {
        float4 v = __ldg(xv + i);
        mn = fminf(mn, fminf(fminf(v.x, v.y), fminf(v.z, v.w)));
        mx = fmaxf(mx, fmaxf(fmaxf(v.x, v.y), fmaxf(v.z, v.w)));
    }
    #pragma unroll
    for (int o = 16; o; o >>= 1) {
        mn = fminf(mn, __shfl_xor_sync(0xffffffffu, mn, o));
        mx = fmaxf(mx, __shfl_xor_sync(0xffffffffu, mx, o));
    }
    __shared__ float smn[8], smx[8];
    int lane = threadIdx.x & 31, wid = threadIdx.x >> 5;
    if (lane == 0) { smn[wid] = mn; smx[wid] = mx; }
    __syncthreads();
    if (wid == 0) {
        mn = smn[lane & 7]; mx = smx[lane & 7];
        #pragma unroll
        for (int o = 4; o; o >>= 1) {
            mn = fminf(mn, __shfl_xor_sync(0xffffffffu, mn, o));
            mx = fmaxf(mx, __shfl_xor_sync(0xffffffffu, mx, o));
        }
        if (lane == 0) {
            atomicMin(&g_minkey[b], f2key(mn));
            atomicMax(&g_maxkey[b], f2key(mx));
        }
    }
}

// ---------------- kernel 2: finalize constants ----------------
__global__ void finK(const float* __restrict__ ols,
                     const float* __restrict__ gamma, const float* __restrict__ beta,
                     const float* __restrict__ mean,  const float* __restrict__ var) {
    int t = threadIdx.x;
    if (t < NCH) {
        float s = gamma[t] * rsqrtf(var[t] + 1e-3f);
        g_bnS[t] = s;
        g_bnT[t] = beta[t] - mean[t] * s;
    }
    if (t < BB) {
        float mn = key2f(g_minkey[t]);
        float mx = key2f(g_maxkey[t]);
        g_xmin[t] = mn;
        g_sA[t]   = 1.0f / (mx - mn + 1e-6f);
    }
    if (t == 0) {
        const float L2 = 0.69314718055994530942f;
        float w[4], lr[4];
        float wsum = 0.f, wlr = 0.f;
        #pragma unroll
        for (int s = 0; s < 4; s++) {
            w[s] = ols[s];
            lr[s] = (float)(s + 1) * L2;
            wsum += w[s];
            wlr  += w[s] * lr[s];
        }
        float lrbar = wlr / wsum;
        float den = 0.f;
        #pragma unroll
        for (int s = 0; s < 4; s++) {
            float dx = lr[s] - lrbar;
            den += w[s] * dx * dx;
        }
        #pragma unroll
        for (int s = 0; s < 4; s++) g_coef[s] = w[s] * (lr[s] - lrbar) / den;
    }
}

// ---------------- horizontal sliding-window scan (one scale) ----------------
// window over cols [C-LO, C+HI]; thread owns (row R, channel ch); accumulates
// coef*log(measure+eps) into per-col alpha registers.
template <int LO, int HI>
__device__ __forceinline__ void scanT(const float* __restrict__ buf, int R, int ch,
                                      float coef, float* __restrict__ alpha) {
    const float* p = buf + R * ROWSTR + ch;
    float ws = 0.f;
    #pragma unroll
    for (int k = -LO; k <= HI; k++) ws += p[(7 + k) * 8];
    #pragma unroll
    for (int j = 0; j < TW; j++) {
        alpha[j] += coef * __logf(ws + 1e-6f);
        if (j < TW - 1) ws += p[(8 + j + HI) * 8] - p[(7 + j - LO) * 8];
    }
}

// ---------------- kernel 3: fused main ----------------
__global__ void __launch_bounds__(256, 1)
mainK(const float* __restrict__ x, const float* __restrict__ anchors,
      const float* __restrict__ widths, float* __restrict__ out) {
    extern __shared__ float sm[];
    float* XS = sm;                       // staged xs tile; later reused for V8
    float* VA = sm + FR * ROWSTR;         // V2, later V16
    float* VB = sm + 2 * FR * ROWSTR;     // V4

    const int tid = threadIdx.x;
    const int b  = blockIdx.z;
    const int cg = blockIdx.y;           // channel group of 8
    const int tx = blockIdx.x % 7, ty = blockIdx.x / 7;
    const int h0 = ty * TH, w0 = tx * TW;
    const int gc = cg * 8;

    const float sA = g_sA[b], xm = g_xmin[b];
    const size_t planeB = (size_t)b * HH * WW * NCH;

    // ---- load 47x47x8 tile (zero-padded, scaled to xs) ----
    for (int i = tid; i < FR * FC * 2; i += 256) {
        int half = i & 1;
        int q = i >> 1;
        int r = q / FC, c = q - r * FC;
        int gh = h0 - 7 + r, gw = w0 - 7 + c;
        float4 v = make_float4(0.f, 0.f, 0.f, 0.f);
        if ((unsigned)gh < (unsigned)HH && (unsigned)gw < (unsigned)WW) {
            v = *reinterpret_cast<const float4*>(
                    x + planeB + ((size_t)gh * WW + gw) * NCH + gc + half * 4);
            v.x = (v.x - xm) * sA; v.y = (v.y - xm) * sA;
            v.z = (v.z - xm) * sA; v.w = (v.w - xm) * sA;
        }
        *reinterpret_cast<float4*>(XS + r * ROWSTR + c * 8 + half * 4) = v;
    }
    __syncthreads();

    // ---- V2 = XS[r] + XS[r+1], rows 0..45 ----
    for (int i = tid; i < 46 * 376; i += 256) {
        int r = i / 376; int cc = i - r * 376;
        VA[r * ROWSTR + cc] = XS[r * ROWSTR + cc] + XS[(r + 1) * ROWSTR + cc];
    }
    __syncthreads();

    float alpha[TW];
    #pragma unroll
    for (int j = 0; j < TW; j++) alpha[j] = 0.f;

    const int ch  = tid & 7;
    const int row = tid >> 3;        // 0..31
    const int R   = 7 + row;
    const float c0 = g_coef[0], c1 = g_coef[1], c2 = g_coef[2], c3 = g_coef[3];

    // scale 2
    scanT<0, 1>(VA, R, ch, c0, alpha);

    // V4 = V2[r-1] + V2[r+1], rows 1..44
    for (int i = tid; i < 44 * 376; i += 256) {
        int r = 1 + i / 376; int cc = i - (r - 1) * 376;
        VB[r * ROWSTR + cc] = VA[(r - 1) * ROWSTR + cc] + VA[(r + 1) * ROWSTR + cc];
    }
    __syncthreads();

    // scale 4
    scanT<1, 2>(VB, R, ch, c1, alpha);

    // V8 = V4[r-2] + V4[r+2], rows 3..42  (into XS buffer, now free)
    for (int i = tid; i < 40 * 376; i += 256) {
        int r = 3 + i / 376; int cc = i - (r - 3) * 376;
        XS[r * ROWSTR + cc] = VB[(r - 2) * ROWSTR + cc] + VB[(r + 2) * ROWSTR + cc];
    }
    __syncthreads();

    // scale 8
    scanT<3, 4>(XS, R, ch, c2, alpha);

    // V16 = V8[r-4] + V8[r+4], rows 7..38  (into VA buffer, now free)
    for (int i = tid; i < 32 * 376; i += 256) {
        int r = 7 + i / 376; int cc = i - (r - 7) * 376;
        VA[r * ROWSTR + cc] = XS[(r - 4) * ROWSTR + cc] + XS[(r + 4) * ROWSTR + cc];
    }
    __syncthreads();

    // scale 16
    scanT<7, 8>(VA, R, ch, c3, alpha);

    // ---- per-pixel epilogue: BN -> soft histogram -> sigmoid -> add x ----
    const int gcc = gc + ch;
    float A[8], W8[8];
    #pragma unroll
    for (int k = 0; k < 8; k++) {
        A[k]  = __ldg(anchors + gcc * 8 + k);
        W8[k] = __ldg(widths  + gcc * 8 + k);
    }
    const float bnS = g_bnS[gcc], bnT = g_bnT[gcc];
    const int gh = h0 + row;
    const size_t base = planeB + ((size_t)gh * WW + w0) * NCH + gcc;

    #pragma unroll
    for (int j = 0; j < TW; j++) {
        float a = fmaf(alpha[j], bnS, bnT);
        float t = 0.f;
        #pragma unroll
        for (int k = 0; k < 8; k++) {
            float d = fabsf(a - A[k]);
            t += fmaxf(fmaf(-W8[k], d, 1.0f), 0.0f);
        }
        float sig = __fdividef(1.0f, 1.0f + __expf(-t));
        out[base + (size_t)j * NCH] = __ldg(x + base + (size_t)j * NCH) + sig;
    }
}

// ---------------- launch ----------------
extern "C" void kernel_launch(void* const* d_in, const int* in_sizes, int n_in,
                              void* d_out, int out_size) {
    const float* x       = (const float*)d_in[0];
    const float* ols     = (const float*)d_in[1];
    const float* anchors = (const float*)d_in[2];
    const float* widths  = (const float*)d_in[3];
    const float* gamma   = (const float*)d_in[4];
    const float* beta    = (const float*)d_in[5];
    const float* mean    = (const float*)d_in[6];
    const float* var     = (const float*)d_in[7];
    float* out = (float*)d_out;

    cudaFuncSetAttribute(mainK, cudaFuncAttributeMaxDynamicSharedMemorySize, SMEM_BYTES);

    initK<<<1, 32>>>();
    minmaxK<<<dim3(128, BB), 256>>>(x);
    finK<<<1, 64>>>(ols, gamma, beta, mean, var);
    mainK<<<dim3(49, 8, BB), 256, SMEM_BYTES>>>(x, anchors, widths, out);
}

// round 2
// speedup vs baseline: 1.4001x; 1.4001x over previous
#include <cuda_runtime.h>

#define HH 224
#define WW 224
#define NCH 64
#define BB 4

#define TH 32
#define TW 16
#define FR 47            // TH + 15 halo rows
#define FC 31            // TW + 15 halo cols
#define ROWSTR 264       // floats per row: 31*8=248 padded to 264 (264%32==8 -> conflict-free)
#define ROWSTR4 66       // ROWSTR/4
#define SMEM_BYTES (2 * FR * ROWSTR * 4)

// ---------------- device globals (scratch; no allocation) ----------------
__device__ unsigned g_minkey[BB];
__device__ unsigned g_maxkey[BB];
__device__ float    g_sA[BB];      // 1/(max-min+eps)
__device__ float    g_xmin[BB];
__device__ float    g_coef[4];     // OLS coefficients c_s
__device__ float    g_bnS[NCH];    // folded BN scale
__device__ float    g_bnT[NCH];    // folded BN bias

__device__ __forceinline__ unsigned f2key(float f) {
    unsigned u = __float_as_uint(f);
    return (u & 0x80000000u) ? ~u : (u | 0x80000000u);
}
__device__ __forceinline__ float key2f(unsigned k) {
    unsigned u = (k & 0x80000000u) ? (k & 0x7FFFFFFFu) : ~k;
    return __uint_as_float(u);
}

// ---------------- kernel 0: reset atomic scratch ----------------
__global__ void initK() {
    int t = threadIdx.x;
    if (t < BB) { g_minkey[t] = 0xFFFFFFFFu; g_maxkey[t] = 0u; }
}

// ---------------- kernel 1: per-sample min/max ----------------
__global__ void minmaxK(const float* __restrict__ x) {
    const int b = blockIdx.y;
    const int n4 = HH * WW * NCH / 4;
    const float4* xv = reinterpret_cast<const float4*>(x) + (size_t)b * n4;

    float mn = 3.402823466e38f, mx = -3.402823466e38f;
    for (int i = blockIdx.x * blockDim.x + threadIdx.x; i < n4; i += gridDim.x * blockDim.x) {
        float4 v = __ldg(xv + i);
        mn = fminf(mn, fminf(fminf(v.x, v.y), fminf(v.z, v.w)));
        mx = fmaxf(mx, fmaxf(fmaxf(v.x, v.y), fmaxf(v.z, v.w)));
    }
    #pragma unroll
    for (int o = 16; o; o >>= 1) {
        mn = fminf(mn, __shfl_xor_sync(0xffffffffu, mn, o));
        mx = fmaxf(mx, __shfl_xor_sync(0xffffffffu, mx, o));
    }
    __shared__ float smn[8], smx[8];
    int lane = threadIdx.x & 31, wid = threadIdx.x >> 5;
    if (lane == 0) { smn[wid] = mn; smx[wid] = mx; }
    __syncthreads();
    if (wid == 0) {
        mn = smn[lane & 7]; mx = smx[lane & 7];
        #pragma unroll
        for (int o = 4; o; o >>= 1) {
            mn = fminf(mn, __shfl_xor_sync(0xffffffffu, mn, o));
            mx = fmaxf(mx, __shfl_xor_sync(0xffffffffu, mx, o));
        }
        if (lane == 0) {
            atomicMin(&g_minkey[b], f2key(mn));
            atomicMax(&g_maxkey[b], f2key(mx));
        }
    }
}

// ---------------- kernel 2: finalize constants ----------------
__global__ void finK(const float* __restrict__ ols,
                     const float* __restrict__ gamma, const float* __restrict__ beta,
                     const float* __restrict__ mean,  const float* __restrict__ var) {
    int t = threadIdx.x;
    if (t < NCH) {
        float s = gamma[t] * rsqrtf(var[t] + 1e-3f);
        g_bnS[t] = s;
        g_bnT[t] = beta[t] - mean[t] * s;
    }
    if (t < BB) {
        float mn = key2f(g_minkey[t]);
        float mx = key2f(g_maxkey[t]);
        g_xmin[t] = mn;
        g_sA[t]   = 1.0f / (mx - mn + 1e-6f);
    }
    if (t == 0) {
        const float L2 = 0.69314718055994530942f;
        float w[4], lr[4];
        float wsum = 0.f, wlr = 0.f;
        #pragma unroll
        for (int s = 0; s < 4; s++) {
            w[s] = ols[s];
            lr[s] = (float)(s + 1) * L2;
            wsum += w[s];
            wlr  += w[s] * lr[s];
        }
        float lrbar = wlr / wsum;
        float den = 0.f;
        #pragma unroll
        for (int s = 0; s < 4; s++) {
            float dx = lr[s] - lrbar;
            den += w[s] * dx * dx;
        }
        #pragma unroll
        for (int s = 0; s < 4; s++) g_coef[s] = w[s] * (lr[s] - lrbar) / den;
    }
}

// ---------------- horizontal sliding-window scan (one scale) ----------------
// window over cols [C-LO, C+HI]; thread owns (row R, channel ch); accumulates
// coef*log(measure+eps) into per-col alpha registers.
template <int LO, int HI>
__device__ __forceinline__ void scanT(const float* __restrict__ buf, int R, int ch,
                                      float coef, float* __restrict__ alpha) {
    const float* p = buf + R * ROWSTR + ch;
    float ws = 0.f;
    #pragma unroll
    for (int k = -LO; k <= HI; k++) ws += p[(7 + k) * 8];
    #pragma unroll
    for (int j = 0; j < TW; j++) {
        alpha[j] += coef * __logf(ws + 1e-6f);
        if (j < TW - 1) ws += p[(8 + j + HI) * 8] - p[(7 + j - LO) * 8];
    }
}

// vertical doubling pass: dst[r] = src[r-OFF] + src[r+OFF], r in [R0, R0+NR)
template <int OFF, int R0, int NR>
__device__ __forceinline__ void vpass(float4* __restrict__ dst, const float4* __restrict__ src,
                                      int tid) {
    for (int i = tid; i < NR * (FC * 2); i += 256) {
        int r = R0 + i / (FC * 2);
        int c = i - (r - R0) * (FC * 2);
        dst[r * ROWSTR4 + c] = make_float4(0.f, 0.f, 0.f, 0.f);
        float4 a = src[(r - OFF) * ROWSTR4 + c];
        float4 b = src[(r + OFF) * ROWSTR4 + c];
        dst[r * ROWSTR4 + c] = make_float4(a.x + b.x, a.y + b.y, a.z + b.z, a.w + b.w);
    }
}

// ---------------- kernel 3: fused main ----------------
__global__ void __launch_bounds__(256, 2)
mainK(const float* __restrict__ x, const float* __restrict__ anchors,
      const float* __restrict__ widths, float* __restrict__ out) {
    extern __shared__ float sm[];
    float* A = sm;                       // XS, then V4, then V16
    float* Bf = sm + FR * ROWSTR;        // V2, then V8
    float4* A4 = reinterpret_cast<float4*>(A);
    float4* B4 = reinterpret_cast<float4*>(Bf);

    const int tid = threadIdx.x;
    const int b  = blockIdx.z;
    const int cg = blockIdx.y;           // channel group of 8
    const int tx = blockIdx.x % (WW / TW), ty = blockIdx.x / (WW / TW);
    const int h0 = ty * TH, w0 = tx * TW;
    const int gc = cg * 8;

    const float sA = g_sA[b], xm = g_xmin[b];
    const size_t planeB = (size_t)b * HH * WW * NCH;

    // ---- load FRxFCx8 tile (zero-padded, scaled to xs) into A ----
    for (int i = tid; i < FR * FC * 2; i += 256) {
        int half = i & 1;
        int q = i >> 1;
        int r = q / FC, c = q - r * FC;
        int gh = h0 - 7 + r, gw = w0 - 7 + c;
        float4 v = make_float4(0.f, 0.f, 0.f, 0.f);
        if ((unsigned)gh < (unsigned)HH && (unsigned)gw < (unsigned)WW) {
            v = *reinterpret_cast<const float4*>(
                    x + planeB + ((size_t)gh * WW + gw) * NCH + gc + half * 4);
            v.x = (v.x - xm) * sA; v.y = (v.y - xm) * sA;
            v.z = (v.z - xm) * sA; v.w = (v.w - xm) * sA;
        }
        *reinterpret_cast<float4*>(A + r * ROWSTR + c * 8 + half * 4) = v;
    }
    __syncthreads();

    // ---- V2 = A[r] + A[r+1] -> B, rows 0..45 ----
    for (int i = tid; i < 46 * (FC * 2); i += 256) {
        int r = i / (FC * 2);
        int c = i - r * (FC * 2);
        float4 a = A4[r * ROWSTR4 + c];
        float4 bb = A4[(r + 1) * ROWSTR4 + c];
        B4[r * ROWSTR4 + c] = make_float4(a.x + bb.x, a.y + bb.y, a.z + bb.z, a.w + bb.w);
    }
    __syncthreads();

    float alpha[TW];
    #pragma unroll
    for (int j = 0; j < TW; j++) alpha[j] = 0.f;

    const int ch  = tid & 7;
    const int row = tid >> 3;        // 0..31
    const int R   = 7 + row;
    const float c0 = g_coef[0], c1 = g_coef[1], c2 = g_coef[2], c3 = g_coef[3];

    // V4 = V2[r-1] + V2[r+1] -> A (XS dead), rows 1..44 ; scan V2 (B)
    vpass<1, 1, 44>(A4, B4, tid);
    scanT<0, 1>(Bf, R, ch, c0, alpha);
    __syncthreads();

    // V8 = V4[r-2] + V4[r+2] -> B (V2 dead), rows 3..42 ; scan V4 (A)
    vpass<2, 3, 40>(B4, A4, tid);
    scanT<1, 2>(A, R, ch, c1, alpha);
    __syncthreads();

    // V16 = V8[r-4] + V8[r+4] -> A (V4 dead), rows 7..38 ; scan V8 (B)
    vpass<4, 7, 32>(A4, B4, tid);
    scanT<3, 4>(Bf, R, ch, c2, alpha);
    __syncthreads();

    // scan V16 (A)
    scanT<7, 8>(A, R, ch, c3, alpha);

    // ---- per-pixel epilogue: BN -> soft histogram -> sigmoid -> add x ----
    const int gcc = gc + ch;
    float AN[8], W8[8];
    #pragma unroll
    for (int k = 0; k < 8; k++) {
        AN[k] = __ldg(anchors + gcc * 8 + k);
        W8[k] = __ldg(widths  + gcc * 8 + k);
    }
    const float bnS = g_bnS[gcc], bnT = g_bnT[gcc];
    const int gh = h0 + row;
    const size_t base = planeB + ((size_t)gh * WW + w0) * NCH + gcc;

    #pragma unroll
    for (int j = 0; j < TW; j++) {
        float a = fmaf(alpha[j], bnS, bnT);
        float t = 0.f;
        #pragma unroll
        for (int k = 0; k < 8; k++) {
            float d = fabsf(a - AN[k]);
            t += fmaxf(fmaf(-W8[k], d, 1.0f), 0.0f);
        }
        float sig = __fdividef(1.0f, 1.0f + __expf(-t));
        out[base + (size_t)j * NCH] = __ldg(x + base + (size_t)j * NCH) + sig;
    }
}

// ---------------- launch ----------------
extern "C" void kernel_launch(void* const* d_in, const int* in_sizes, int n_in,
                              void* d_out, int out_size) {
    const float* x       = (const float*)d_in[0];
    const float* ols     = (const float*)d_in[1];
    const float* anchors = (const float*)d_in[2];
    const float* widths  = (const float*)d_in[3];
    const float* gamma   = (const float*)d_in[4];
    const float* beta    = (const float*)d_in[5];
    const float* mean    = (const float*)d_in[6];
    const float* var     = (const float*)d_in[7];
    float* out = (float*)d_out;

    cudaFuncSetAttribute(mainK, cudaFuncAttributeMaxDynamicSharedMemorySize, SMEM_BYTES);

    initK<<<1, 32>>>();
    minmaxK<<<dim3(128, BB), 256>>>(x);
    finK<<<1, 64>>>(ols, gamma, beta, mean, var);
    mainK<<<dim3((WW / TW) * (HH / TH), 8, BB), 256, SMEM_BYTES>>>(x, anchors, widths, out);
}

// round 3
// speedup vs baseline: 1.5359x; 1.0970x over previous
#include <cuda_runtime.h>

#define HH 224
#define WW 224
#define NCH 64
#define BB 4

#define TH 32
#define TW 16
#define FR 47            // TH + 15 halo rows
#define FC 31            // TW + 15 halo cols
#define ROWSTR 248       // 31*8 floats; 248%32==24 -> 4-row x 8-ch warps conflict-free
#define ROWSTR4 62       // ROWSTR/4
#define SMEM_BYTES (2 * FR * ROWSTR * 4)

// ---------------- device globals (scratch; no allocation) ----------------
__device__ unsigned g_minkey[BB];
__device__ unsigned g_maxkey[BB];
__device__ float    g_sA[BB];      // 1/(max-min+eps)
__device__ float    g_xmin[BB];
__device__ float    g_coef[4];     // OLS coefficients c_s
__device__ float    g_bnS[NCH];    // folded BN scale
__device__ float    g_bnT[NCH];    // folded BN bias

__device__ __forceinline__ unsigned f2key(float f) {
    unsigned u = __float_as_uint(f);
    return (u & 0x80000000u) ? ~u : (u | 0x80000000u);
}
__device__ __forceinline__ float key2f(unsigned k) {
    unsigned u = (k & 0x80000000u) ? (k & 0x7FFFFFFFu) : ~k;
    return __uint_as_float(u);
}

// ---------------- kernel 0: reset atomic scratch ----------------
__global__ void initK() {
    int t = threadIdx.x;
    if (t < BB) { g_minkey[t] = 0xFFFFFFFFu; g_maxkey[t] = 0u; }
}

// ---------------- kernel 1: per-sample min/max ----------------
__global__ void minmaxK(const float* __restrict__ x) {
    const int b = blockIdx.y;
    const int n4 = HH * WW * NCH / 4;
    const float4* xv = reinterpret_cast<const float4*>(x) + (size_t)b * n4;

    float mn = 3.402823466e38f, mx = -3.402823466e38f;
    for (int i = blockIdx.x * blockDim.x + threadIdx.x; i < n4; i += gridDim.x * blockDim.x) {
        float4 v = __ldg(xv + i);
        mn = fminf(mn, fminf(fminf(v.x, v.y), fminf(v.z, v.w)));
        mx = fmaxf(mx, fmaxf(fmaxf(v.x, v.y), fmaxf(v.z, v.w)));
    }
    #pragma unroll
    for (int o = 16; o; o >>= 1) {
        mn = fminf(mn, __shfl_xor_sync(0xffffffffu, mn, o));
        mx = fmaxf(mx, __shfl_xor_sync(0xffffffffu, mx, o));
    }
    __shared__ float smn[8], smx[8];
    int lane = threadIdx.x & 31, wid = threadIdx.x >> 5;
    if (lane == 0) { smn[wid] = mn; smx[wid] = mx; }
    __syncthreads();
    if (wid == 0) {
        mn = smn[lane & 7]; mx = smx[lane & 7];
        #pragma unroll
        for (int o = 4; o; o >>= 1) {
            mn = fminf(mn, __shfl_xor_sync(0xffffffffu, mn, o));
            mx = fmaxf(mx, __shfl_xor_sync(0xffffffffu, mx, o));
        }
        if (lane == 0) {
            atomicMin(&g_minkey[b], f2key(mn));
            atomicMax(&g_maxkey[b], f2key(mx));
        }
    }
}

// ---------------- kernel 2: finalize constants ----------------
__global__ void finK(const float* __restrict__ ols,
                     const float* __restrict__ gamma, const float* __restrict__ beta,
                     const float* __restrict__ mean,  const float* __restrict__ var) {
    int t = threadIdx.x;
    if (t < NCH) {
        float s = gamma[t] * rsqrtf(var[t] + 1e-3f);
        g_bnS[t] = s;
        g_bnT[t] = beta[t] - mean[t] * s;
    }
    if (t < BB) {
        float mn = key2f(g_minkey[t]);
        float mx = key2f(g_maxkey[t]);
        g_xmin[t] = mn;
        g_sA[t]   = 1.0f / (mx - mn + 1e-6f);
    }
    if (t == 0) {
        const float L2 = 0.69314718055994530942f;
        float w[4], lr[4];
        float wsum = 0.f, wlr = 0.f;
        #pragma unroll
        for (int s = 0; s < 4; s++) {
            w[s] = ols[s];
            lr[s] = (float)(s + 1) * L2;
            wsum += w[s];
            wlr  += w[s] * lr[s];
        }
        float lrbar = wlr / wsum;
        float den = 0.f;
        #pragma unroll
        for (int s = 0; s < 4; s++) {
            float dx = lr[s] - lrbar;
            den += w[s] * dx * dx;
        }
        #pragma unroll
        for (int s = 0; s < 4; s++) g_coef[s] = w[s] * (lr[s] - lrbar) / den;
    }
}

// ---------------- register-ring sliding-window scan (one scale) ----------------
// window over cols [C-LO, C+HI]; thread owns (row R, channel ch); 1 LDS per slide.
template <int LO, int HI>
__device__ __forceinline__ void scanR(const float* __restrict__ buf, int R, int ch,
                                      float coef, float* __restrict__ alpha) {
    constexpr int W = LO + HI + 1;
    const float* p = buf + R * ROWSTR + ch;
    float ring[W];
    float ws = 0.f;
    #pragma unroll
    for (int k = 0; k < W; k++) { ring[k] = p[(7 - LO + k) * 8]; ws += ring[k]; }
    #pragma unroll
    for (int j = 0; j < TW; j++) {
        alpha[j] += coef * __logf(ws + 1e-6f);
        if (j < TW - 1) {
            float nv = p[(8 + j + HI) * 8];
            ws += nv - ring[j % W];
            ring[j % W] = nv;
        }
    }
}

// scale-16 scan reading V8 at rows R-4 and R+4 (V16 never materialized)
__device__ __forceinline__ void scanR16(const float* __restrict__ buf, int R, int ch,
                                        float coef, float* __restrict__ alpha) {
    const float* pa = buf + (R - 4) * ROWSTR + ch;
    const float* pb = buf + (R + 4) * ROWSTR + ch;
    float ring[16];
    float ws = 0.f;
    #pragma unroll
    for (int k = 0; k < 16; k++) { ring[k] = pa[k * 8] + pb[k * 8]; ws += ring[k]; }
    #pragma unroll
    for (int j = 0; j < TW; j++) {
        alpha[j] += coef * __logf(ws + 1e-6f);
        if (j < TW - 1) {
            float nv = pa[(16 + j) * 8] + pb[(16 + j) * 8];
            ws += nv - ring[j % 16];
            ring[j % 16] = nv;
        }
    }
}

// vertical doubling pass: dst[r] = src[r-OFF] + src[r+OFF], r in [R0, R0+NR)
template <int OFF, int R0, int NR>
__device__ __forceinline__ void vpass(float4* __restrict__ dst, const float4* __restrict__ src,
                                      int tid) {
    for (int i = tid; i < NR * ROWSTR4; i += 256) {
        int r = R0 + i / ROWSTR4;
        int c = i - (r - R0) * ROWSTR4;
        float4 a = src[(r - OFF) * ROWSTR4 + c];
        float4 b = src[(r + OFF) * ROWSTR4 + c];
        dst[r * ROWSTR4 + c] = make_float4(a.x + b.x, a.y + b.y, a.z + b.z, a.w + b.w);
    }
}

// ---------------- kernel 3: fused main ----------------
__global__ void __launch_bounds__(256, 2)
mainK(const float* __restrict__ x, const float* __restrict__ anchors,
      const float* __restrict__ widths, float* __restrict__ out) {
    extern __shared__ float sm[];
    float* A  = sm;                      // V4
    float* Bf = sm + FR * ROWSTR;        // V2, then V8
    float4* A4 = reinterpret_cast<float4*>(A);
    float4* B4 = reinterpret_cast<float4*>(Bf);

    const int tid = threadIdx.x;
    const int b  = blockIdx.z;
    const int cg = blockIdx.y;           // channel group of 8
    const int tx = blockIdx.x % (WW / TW), ty = blockIdx.x / (WW / TW);
    const int h0 = ty * TH, w0 = tx * TW;
    const int gc = cg * 8;

    const float sA = g_sA[b], xm = g_xmin[b];
    const size_t planeB = (size_t)b * HH * WW * NCH;

    // ---- phase 1: fused load + scale + V2 -> B, rows 0..45 ----
    for (int i = tid; i < 46 * FC * 2; i += 256) {
        int r = i / (FC * 2);
        int q = i - r * (FC * 2);
        int c = q >> 1, half = q & 1;
        int gh0 = h0 - 7 + r;
        int gw  = w0 - 7 + c;
        float4 s0 = make_float4(0.f, 0.f, 0.f, 0.f);
        float4 s1 = s0;
        if ((unsigned)gw < (unsigned)WW) {
            if ((unsigned)gh0 < (unsigned)HH) {
                float4 v = *reinterpret_cast<const float4*>(
                        x + planeB + ((size_t)gh0 * WW + gw) * NCH + gc + half * 4);
                s0 = make_float4((v.x - xm) * sA, (v.y - xm) * sA,
                                 (v.z - xm) * sA, (v.w - xm) * sA);
            }
            if ((unsigned)(gh0 + 1) < (unsigned)HH) {
                float4 v = *reinterpret_cast<const float4*>(
                        x + planeB + ((size_t)(gh0 + 1) * WW + gw) * NCH + gc + half * 4);
                s1 = make_float4((v.x - xm) * sA, (v.y - xm) * sA,
                                 (v.z - xm) * sA, (v.w - xm) * sA);
            }
        }
        *reinterpret_cast<float4*>(Bf + r * ROWSTR + c * 8 + half * 4) =
            make_float4(s0.x + s1.x, s0.y + s1.y, s0.z + s1.z, s0.w + s1.w);
    }
    __syncthreads();

    float alpha[TW];
    #pragma unroll
    for (int j = 0; j < TW; j++) alpha[j] = 0.f;

    const int ch  = tid & 7;
    const int row = tid >> 3;        // 0..31
    const int R   = 7 + row;
    const float c0 = g_coef[0], c1 = g_coef[1], c2 = g_coef[2], c3 = g_coef[3];

    // ---- phase 2: V4 = V2[r-1]+V2[r+1] -> A (rows 1..44); scan V2 (B) ----
    vpass<1, 1, 44>(A4, B4, tid);
    scanR<0, 1>(Bf, R, ch, c0, alpha);
    __syncthreads();

    // ---- phase 3: V8 = V4[r-2]+V4[r+2] -> B (rows 3..42); scan V4 (A) ----
    vpass<2, 3, 40>(B4, A4, tid);
    scanR<1, 2>(A, R, ch, c1, alpha);
    __syncthreads();

    // ---- phase 4: scan V8 (B, row R) and V16 (B, rows R+-4, fused) ----
    scanR<3, 4>(Bf, R, ch, c2, alpha);
    scanR16(Bf, R, ch, c3, alpha);

    // ---- per-pixel epilogue: BN -> soft histogram -> sigmoid -> add x ----
    const int gcc = gc + ch;
    float AN[8], W8[8];
    #pragma unroll
    for (int k = 0; k < 8; k++) {
        AN[k] = __ldg(anchors + gcc * 8 + k);
        W8[k] = __ldg(widths  + gcc * 8 + k);
    }
    const float bnS = g_bnS[gcc], bnT = g_bnT[gcc];
    const int gh = h0 + row;
    const size_t base = planeB + ((size_t)gh * WW + w0) * NCH + gcc;

    #pragma unroll
    for (int j = 0; j < TW; j++) {
        float a = fmaf(alpha[j], bnS, bnT);
        float t = 0.f;
        #pragma unroll
        for (int k = 0; k < 8; k++) {
            float d = fabsf(a - AN[k]);
            t += fmaxf(fmaf(-W8[k], d, 1.0f), 0.0f);
        }
        float sig = __fdividef(1.0f, 1.0f + __expf(-t));
        out[base + (size_t)j * NCH] = __ldg(x + base + (size_t)j * NCH) + sig;
    }
}

// ---------------- launch ----------------
extern "C" void kernel_launch(void* const* d_in, const int* in_sizes, int n_in,
                              void* d_out, int out_size) {
    const float* x       = (const float*)d_in[0];
    const float* ols     = (const float*)d_in[1];
    const float* anchors = (const float*)d_in[2];
    const float* widths  = (const float*)d_in[3];
    const float* gamma   = (const float*)d_in[4];
    const float* beta    = (const float*)d_in[5];
    const float* mean    = (const float*)d_in[6];
    const float* var     = (const float*)d_in[7];
    float* out = (float*)d_out;

    cudaFuncSetAttribute(mainK, cudaFuncAttributeMaxDynamicSharedMemorySize, SMEM_BYTES);

    initK<<<1, 32>>>();
    minmaxK<<<dim3(128, BB), 256>>>(x);
    finK<<<1, 64>>>(ols, gamma, beta, mean, var);
    mainK<<<dim3((WW / TW) * (HH / TH), 8, BB), 256, SMEM_BYTES>>>(x, anchors, widths, out);
}

// round 4
// speedup vs baseline: 1.8235x; 1.1873x over previous
#include <cuda_runtime.h>

#define HH 224
#define WW 224
#define NCH 64
#define BB 4

#define TH 32
#define TW 16
#define FR 47            // TH + 15 halo rows
#define FC 31            // TW + 15 halo cols
#define ROWSTR 248       // 31*8 floats; 248%32==24 -> 4-row x 8-ch warps conflict-free
#define ROWSTR4 62       // ROWSTR/4
#define V2ROWS 46
#define V8ROWS 40        // V8 rows 3..42 stored at offset (r-3)
#define SMEM_BYTES ((V2ROWS + V8ROWS) * ROWSTR * 4)

// ---------------- device globals (scratch; no allocation) ----------------
__device__ unsigned g_minkey[BB];
__device__ unsigned g_maxkey[BB];
__device__ float    g_sA[BB];      // 1/(max-min+eps)
__device__ float    g_xmin[BB];
__device__ float    g_coef[4];     // OLS coefficients c_s
__device__ float    g_bnS[NCH];    // folded BN scale
__device__ float    g_bnT[NCH];    // folded BN bias

__device__ __forceinline__ unsigned f2key(float f) {
    unsigned u = __float_as_uint(f);
    return (u & 0x80000000u) ? ~u : (u | 0x80000000u);
}
__device__ __forceinline__ float key2f(unsigned k) {
    unsigned u = (k & 0x80000000u) ? (k & 0x7FFFFFFFu) : ~k;
    return __uint_as_float(u);
}

// ---------------- kernel 0: reset atomic scratch ----------------
__global__ void initK() {
    int t = threadIdx.x;
    if (t < BB) { g_minkey[t] = 0xFFFFFFFFu; g_maxkey[t] = 0u; }
}

// ---------------- kernel 1: per-sample min/max ----------------
__global__ void minmaxK(const float* __restrict__ x) {
    const int b = blockIdx.y;
    const int n4 = HH * WW * NCH / 4;
    const float4* xv = reinterpret_cast<const float4*>(x) + (size_t)b * n4;

    float mn = 3.402823466e38f, mx = -3.402823466e38f;
    for (int i = blockIdx.x * blockDim.x + threadIdx.x; i < n4; i += gridDim.x * blockDim.x) {
        float4 v = __ldg(xv + i);
        mn = fminf(mn, fminf(fminf(v.x, v.y), fminf(v.z, v.w)));
        mx = fmaxf(mx, fmaxf(fmaxf(v.x, v.y), fmaxf(v.z, v.w)));
    }
    #pragma unroll
    for (int o = 16; o; o >>= 1) {
        mn = fminf(mn, __shfl_xor_sync(0xffffffffu, mn, o));
        mx = fmaxf(mx, __shfl_xor_sync(0xffffffffu, mx, o));
    }
    __shared__ float smn[8], smx[8];
    int lane = threadIdx.x & 31, wid = threadIdx.x >> 5;
    if (lane == 0) { smn[wid] = mn; smx[wid] = mx; }
    __syncthreads();
    if (wid == 0) {
        mn = smn[lane & 7]; mx = smx[lane & 7];
        #pragma unroll
        for (int o = 4; o; o >>= 1) {
            mn = fminf(mn, __shfl_xor_sync(0xffffffffu, mn, o));
            mx = fmaxf(mx, __shfl_xor_sync(0xffffffffu, mx, o));
        }
        if (lane == 0) {
            atomicMin(&g_minkey[b], f2key(mn));
            atomicMax(&g_maxkey[b], f2key(mx));
        }
    }
}

// ---------------- kernel 2: finalize constants ----------------
__global__ void finK(const float* __restrict__ ols,
                     const float* __restrict__ gamma, const float* __restrict__ beta,
                     const float* __restrict__ mean,  const float* __restrict__ var) {
    int t = threadIdx.x;
    if (t < NCH) {
        float s = gamma[t] * rsqrtf(var[t] + 1e-3f);
        g_bnS[t] = s;
        g_bnT[t] = beta[t] - mean[t] * s;
    }
    if (t < BB) {
        float mn = key2f(g_minkey[t]);
        float mx = key2f(g_maxkey[t]);
        g_xmin[t] = mn;
        g_sA[t]   = 1.0f / (mx - mn + 1e-6f);
    }
    if (t == 0) {
        const float L2 = 0.69314718055994530942f;
        float w[4], lr[4];
        float wsum = 0.f, wlr = 0.f;
        #pragma unroll
        for (int s = 0; s < 4; s++) {
            w[s] = ols[s];
            lr[s] = (float)(s + 1) * L2;
            wsum += w[s];
            wlr  += w[s] * lr[s];
        }
        float lrbar = wlr / wsum;
        float den = 0.f;
        #pragma unroll
        for (int s = 0; s < 4; s++) {
            float dx = lr[s] - lrbar;
            den += w[s] * dx * dx;
        }
        #pragma unroll
        for (int s = 0; s < 4; s++) g_coef[s] = w[s] * (lr[s] - lrbar) / den;
    }
}

// ---------------- register-ring sliding-window scan, single row ----------------
// window over cols [C-LO, C+HI]; thread owns (row base p); 1 LDS per slide.
template <int LO, int HI>
__device__ __forceinline__ void scanR(const float* __restrict__ p,
                                      float coef, float* __restrict__ alpha) {
    constexpr int W = LO + HI + 1;
    float ring[W];
    float ws = 0.f;
    #pragma unroll
    for (int k = 0; k < W; k++) { ring[k] = p[(7 - LO + k) * 8]; ws += ring[k]; }
    #pragma unroll
    for (int j = 0; j < TW; j++) {
        alpha[j] += coef * __logf(ws + 1e-6f);
        if (j < TW - 1) {
            float nv = p[(8 + j + HI) * 8];
            ws += nv - ring[j % W];
            ring[j % W] = nv;
        }
    }
}

// dual-row variant: values are pa[col] + pb[col] (vertical pair never materialized)
template <int LO, int HI>
__device__ __forceinline__ void scanP(const float* __restrict__ pa,
                                      const float* __restrict__ pb,
                                      float coef, float* __restrict__ alpha) {
    constexpr int W = LO + HI + 1;
    float ring[W];
    float ws = 0.f;
    #pragma unroll
    for (int k = 0; k < W; k++) {
        ring[k] = pa[(7 - LO + k) * 8] + pb[(7 - LO + k) * 8];
        ws += ring[k];
    }
    #pragma unroll
    for (int j = 0; j < TW; j++) {
        alpha[j] += coef * __logf(ws + 1e-6f);
        if (j < TW - 1) {
            float nv = pa[(8 + j + HI) * 8] + pb[(8 + j + HI) * 8];
            ws += nv - ring[j % W];
            ring[j % W] = nv;
        }
    }
}

// ---------------- kernel 3: fused main ----------------
__global__ void __launch_bounds__(256, 2)
mainK(const float* __restrict__ x, const float* __restrict__ anchors,
      const float* __restrict__ widths, float* __restrict__ out) {
    extern __shared__ float sm[];
    float* V2 = sm;                        // rows 0..45
    float* V8 = sm + V2ROWS * ROWSTR;      // rows 3..42 stored at (r-3)
    float4* V2v = reinterpret_cast<float4*>(V2);
    float4* V8v = reinterpret_cast<float4*>(V8);

    const int tid = threadIdx.x;
    const int b  = blockIdx.z;
    const int cg = blockIdx.y;           // channel group of 8
    const int tx = blockIdx.x % (WW / TW), ty = blockIdx.x / (WW / TW);
    const int h0 = ty * TH, w0 = tx * TW;
    const int gc = cg * 8;

    const float sA = g_sA[b], xm = g_xmin[b];
    const size_t planeB = (size_t)b * HH * WW * NCH;

    // ---- phase 1: row-walking load + scale + V2 (each x row loaded once) ----
    {
        const int slot = tid % (FC * 2);   // 0..61: (c, half)
        const int rb   = tid / (FC * 2);   // 0..4; rb<4 active
        if (rb < 4) {
            const int r0 = rb * 12;
            const int r1 = (rb == 3) ? V2ROWS : r0 + 12;
            const int c = slot >> 1, half = slot & 1;
            const int gw = w0 - 7 + c;
            const bool wok = (unsigned)gw < (unsigned)WW;
            const float* px = x + planeB + (size_t)gw * NCH + gc + half * 4;

            float4 prev = make_float4(0.f, 0.f, 0.f, 0.f);
            {
                int gh = h0 - 7 + r0;
                if (wok && (unsigned)gh < (unsigned)HH) {
                    float4 v = *reinterpret_cast<const float4*>(px + (size_t)gh * (WW * NCH));
                    prev = make_float4((v.x - xm) * sA, (v.y - xm) * sA,
                                       (v.z - xm) * sA, (v.w - xm) * sA);
                }
            }
            for (int r = r0; r < r1; r++) {
                int gh = h0 - 7 + r + 1;
                float4 cur = make_float4(0.f, 0.f, 0.f, 0.f);
                if (wok && (unsigned)gh < (unsigned)HH) {
                    float4 v = *reinterpret_cast<const float4*>(px + (size_t)gh * (WW * NCH));
                    cur = make_float4((v.x - xm) * sA, (v.y - xm) * sA,
                                      (v.z - xm) * sA, (v.w - xm) * sA);
                }
                *reinterpret_cast<float4*>(V2 + r * ROWSTR + c * 8 + half * 4) =
                    make_float4(prev.x + cur.x, prev.y + cur.y,
                                prev.z + cur.z, prev.w + cur.w);
                prev = cur;
            }
        }
    }
    __syncthreads();

    float alpha[TW];
    #pragma unroll
    for (int j = 0; j < TW; j++) alpha[j] = 0.f;

    const int ch  = tid & 7;
    const int row = tid >> 3;        // 0..31
    const int R   = 7 + row;
    const float c0 = g_coef[0], c1 = g_coef[1], c2 = g_coef[2], c3 = g_coef[3];

    // ---- phase 2: V8[r] = V2[r-3]+V2[r-1]+V2[r+1]+V2[r+3], rows 3..42 ----
    for (int i = tid; i < V8ROWS * ROWSTR4; i += 256) {
        int rr = i / ROWSTR4;            // 0..39 -> r = rr+3
        int c  = i - rr * ROWSTR4;
        int r  = rr + 3;
        float4 a = V2v[(r - 3) * ROWSTR4 + c];
        float4 bb = V2v[(r - 1) * ROWSTR4 + c];
        float4 cc = V2v[(r + 1) * ROWSTR4 + c];
        float4 dd = V2v[(r + 3) * ROWSTR4 + c];
        V8v[rr * ROWSTR4 + c] = make_float4(a.x + bb.x + cc.x + dd.x,
                                            a.y + bb.y + cc.y + dd.y,
                                            a.z + bb.z + cc.z + dd.z,
                                            a.w + bb.w + cc.w + dd.w);
    }
    // scans over V2 (scale 2 at row R; scale 4 = rows R-1,R+1)
    scanR<0, 1>(V2 + R * ROWSTR + ch, c0, alpha);
    scanP<1, 2>(V2 + (R - 1) * ROWSTR + ch, V2 + (R + 1) * ROWSTR + ch, c1, alpha);
    __syncthreads();

    // ---- phase 3: scans over V8 (scale 8 at R; scale 16 = rows R-4,R+4) ----
    scanR<3, 4>(V8 + (R - 3) * ROWSTR + ch, c2, alpha);
    scanP<7, 8>(V8 + (R - 7) * ROWSTR + ch, V8 + (R + 1) * ROWSTR + ch, c3, alpha);

    // ---- per-pixel epilogue: BN -> soft histogram -> sigmoid -> add x ----
    const int gcc = gc + ch;
    float AN[8], W8[8];
    #pragma unroll
    for (int k = 0; k < 8; k++) {
        AN[k] = __ldg(anchors + gcc * 8 + k);
        W8[k] = __ldg(widths  + gcc * 8 + k);
    }
    const float bnS = g_bnS[gcc], bnT = g_bnT[gcc];
    const int gh = h0 + row;
    const size_t base = planeB + ((size_t)gh * WW + w0) * NCH + gcc;

    #pragma unroll
    for (int j = 0; j < TW; j++) {
        float a = fmaf(alpha[j], bnS, bnT);
        float t = 0.f;
        #pragma unroll
        for (int k = 0; k < 8; k++) {
            float d = fabsf(a - AN[k]);
            t += fmaxf(fmaf(-W8[k], d, 1.0f), 0.0f);
        }
        float sig = __fdividef(1.0f, 1.0f + __expf(-t));
        out[base + (size_t)j * NCH] = __ldg(x + base + (size_t)j * NCH) + sig;
    }
}

// ---------------- launch ----------------
extern "C" void kernel_launch(void* const* d_in, const int* in_sizes, int n_in,
                              void* d_out, int out_size) {
    const float* x       = (const float*)d_in[0];
    const float* ols     = (const float*)d_in[1];
    const float* anchors = (const float*)d_in[2];
    const float* widths  = (const float*)d_in[3];
    const float* gamma   = (const float*)d_in[4];
    const float* beta    = (const float*)d_in[5];
    const float* mean    = (const float*)d_in[6];
    const float* var     = (const float*)d_in[7];
    float* out = (float*)d_out;

    cudaFuncSetAttribute(mainK, cudaFuncAttributeMaxDynamicSharedMemorySize, SMEM_BYTES);

    initK<<<1, 32>>>();
    minmaxK<<<dim3(128, BB), 256>>>(x);
    finK<<<1, 64>>>(ols, gamma, beta, mean, var);
    mainK<<<dim3((WW / TW) * (HH / TH), 8, BB), 256, SMEM_BYTES>>>(x, anchors, widths, out);
}

// round 5
// speedup vs baseline: 2.0165x; 1.1059x over previous
#include <cuda_runtime.h>

#define HH 224
#define WW 224
#define NCH 64
#define BB 4

#define TH 32
#define TW 16
#define FC 31            // TW + 15 halo cols
#define ROWSTR 248       // 31*8 floats; 248%32==24 -> 4-row x 8-ch warps conflict-free
#define V2ROWS 46
#define V8ROWS 40        // V8 rows 3..42 stored at offset (r-3)
#define SMEM_BYTES ((V2ROWS + V8ROWS) * ROWSTR * 4)

// ---------------- device globals (scratch; no allocation) ----------------
__device__ unsigned g_minkey[BB];
__device__ unsigned g_maxkey[BB];
__device__ float    g_sA[BB];      // 1/(max-min+eps)
__device__ float    g_xmin[BB];
__device__ float    g_coef[4];     // OLS coefficients c_s
__device__ float    g_bnS[NCH];    // folded BN scale
__device__ float    g_bnT[NCH];    // folded BN bias

__device__ __forceinline__ unsigned f2key(float f) {
    unsigned u = __float_as_uint(f);
    return (u & 0x80000000u) ? ~u : (u | 0x80000000u);
}
__device__ __forceinline__ float key2f(unsigned k) {
    unsigned u = (k & 0x80000000u) ? (k & 0x7FFFFFFFu) : ~k;
    return __uint_as_float(u);
}

// ---------------- kernel 0: reset atomic scratch ----------------
__global__ void initK() {
    int t = threadIdx.x;
    if (t < BB) { g_minkey[t] = 0xFFFFFFFFu; g_maxkey[t] = 0u; }
}

// ---------------- kernel 1: per-sample min/max ----------------
__global__ void minmaxK(const float* __restrict__ x) {
    const int b = blockIdx.y;
    const int n4 = HH * WW * NCH / 4;
    const float4* xv = reinterpret_cast<const float4*>(x) + (size_t)b * n4;

    float mn = 3.402823466e38f, mx = -3.402823466e38f;
    for (int i = blockIdx.x * blockDim.x + threadIdx.x; i < n4; i += gridDim.x * blockDim.x) {
        float4 v = __ldg(xv + i);
        mn = fminf(mn, fminf(fminf(v.x, v.y), fminf(v.z, v.w)));
        mx = fmaxf(mx, fmaxf(fmaxf(v.x, v.y), fmaxf(v.z, v.w)));
    }
    #pragma unroll
    for (int o = 16; o; o >>= 1) {
        mn = fminf(mn, __shfl_xor_sync(0xffffffffu, mn, o));
        mx = fmaxf(mx, __shfl_xor_sync(0xffffffffu, mx, o));
    }
    __shared__ float smn[8], smx[8];
    int lane = threadIdx.x & 31, wid = threadIdx.x >> 5;
    if (lane == 0) { smn[wid] = mn; smx[wid] = mx; }
    __syncthreads();
    if (wid == 0) {
        mn = smn[lane & 7]; mx = smx[lane & 7];
        #pragma unroll
        for (int o = 4; o; o >>= 1) {
            mn = fminf(mn, __shfl_xor_sync(0xffffffffu, mn, o));
            mx = fmaxf(mx, __shfl_xor_sync(0xffffffffu, mx, o));
        }
        if (lane == 0) {
            atomicMin(&g_minkey[b], f2key(mn));
            atomicMax(&g_maxkey[b], f2key(mx));
        }
    }
}

// ---------------- kernel 2: finalize constants ----------------
__global__ void finK(const float* __restrict__ ols,
                     const float* __restrict__ gamma, const float* __restrict__ beta,
                     const float* __restrict__ mean,  const float* __restrict__ var) {
    int t = threadIdx.x;
    if (t < NCH) {
        float s = gamma[t] * rsqrtf(var[t] + 1e-3f);
        g_bnS[t] = s;
        g_bnT[t] = beta[t] - mean[t] * s;
    }
    if (t < BB) {
        float mn = key2f(g_minkey[t]);
        float mx = key2f(g_maxkey[t]);
        g_xmin[t] = mn;
        g_sA[t]   = 1.0f / (mx - mn + 1e-6f);
    }
    if (t == 0) {
        const float L2 = 0.69314718055994530942f;
        float w[4], lr[4];
        float wsum = 0.f, wlr = 0.f;
        #pragma unroll
        for (int s = 0; s < 4; s++) {
            w[s] = ols[s];
            lr[s] = (float)(s + 1) * L2;
            wsum += w[s];
            wlr  += w[s] * lr[s];
        }
        float lrbar = wlr / wsum;
        float den = 0.f;
        #pragma unroll
        for (int s = 0; s < 4; s++) {
            float dx = lr[s] - lrbar;
            den += w[s] * dx * dx;
        }
        #pragma unroll
        for (int s = 0; s < 4; s++) g_coef[s] = w[s] * (lr[s] - lrbar) / den;
    }
}

// ---------------- register-ring sliding-window scan, single row ----------------
template <int LO, int HI>
__device__ __forceinline__ void scanR(const float* __restrict__ p,
                                      float coef, float* __restrict__ alpha) {
    constexpr int W = LO + HI + 1;
    float ring[W];
    float ws = 0.f;
    #pragma unroll
    for (int k = 0; k < W; k++) { ring[k] = p[(7 - LO + k) * 8]; ws += ring[k]; }
    #pragma unroll
    for (int j = 0; j < TW; j++) {
        alpha[j] += coef * __logf(ws + 1e-6f);
        if (j < TW - 1) {
            float nv = p[(8 + j + HI) * 8];
            ws += nv - ring[j % W];
            ring[j % W] = nv;
        }
    }
}

// dual-row variant: values are pa[col] + pb[col] (vertical pair never materialized)
template <int LO, int HI>
__device__ __forceinline__ void scanP(const float* __restrict__ pa,
                                      const float* __restrict__ pb,
                                      float coef, float* __restrict__ alpha) {
    constexpr int W = LO + HI + 1;
    float ring[W];
    float ws = 0.f;
    #pragma unroll
    for (int k = 0; k < W; k++) {
        ring[k] = pa[(7 - LO + k) * 8] + pb[(7 - LO + k) * 8];
        ws += ring[k];
    }
    #pragma unroll
    for (int j = 0; j < TW; j++) {
        alpha[j] += coef * __logf(ws + 1e-6f);
        if (j < TW - 1) {
            float nv = pa[(8 + j + HI) * 8] + pb[(8 + j + HI) * 8];
            ws += nv - ring[j % W];
            ring[j % W] = nv;
        }
    }
}

// ---------------- kernel 3: fused main ----------------
__global__ void __launch_bounds__(256, 2)
mainK(const float* __restrict__ x, const float* __restrict__ anchors,
      const float* __restrict__ widths, float* __restrict__ out) {
    extern __shared__ float sm[];
    float* V2 = sm;                        // rows 0..45
    float* V8 = sm + V2ROWS * ROWSTR;      // rows 3..42 stored at (r-3)

    const int tid = threadIdx.x;
    const int b  = blockIdx.z;
    const int cg = blockIdx.y;           // channel group of 8
    const int tx = blockIdx.x % (WW / TW), ty = blockIdx.x / (WW / TW);
    const int h0 = ty * TH, w0 = tx * TW;
    const int gc = cg * 8;

    const float sA = g_sA[b], xm = g_xmin[b];
    const size_t planeB = (size_t)b * HH * WW * NCH;

    // ---- phase 1: column walkers emit V2 and V8 directly from x ----
    // 248 walkers: 124 float2 col-slots x 2 row-halves (27 x-rows each).
    if (tid < 248) {
        const int slot = tid % 124;
        const int half = tid / 124;
        const int xr0  = half ? 20 : 0;      // first x tile-row walked
        const int v_lo = half ? 23 : 0,  v_hi = half ? 46 : 23;
        const int e_lo = half ? 23 : 3,  e_hi = half ? 43 : 23;
        const int c = slot >> 2;             // spatial col 0..30
        const int q = slot & 3;              // float2 within 8-ch group
        const int gw = w0 - 7 + c;
        const bool wok = (unsigned)gw < (unsigned)WW;
        const float* px = x + planeB + (size_t)gw * NCH + gc + q * 2;
        float* dst2 = V2 + slot * 2;
        float* dst8 = V8 + slot * 2;

        float2 ring[8];
        #pragma unroll
        for (int t = 0; t < 27; t++) {
            int gh = h0 - 7 + xr0 + t;
            float2 cur = make_float2(0.f, 0.f);
            if (wok && (unsigned)gh < (unsigned)HH) {
                float2 v = *reinterpret_cast<const float2*>(px + (size_t)gh * (WW * NCH));
                cur = make_float2((v.x - xm) * sA, (v.y - xm) * sA);
            }
            ring[t & 7] = cur;
            int xr = xr0 + t;
            int v = xr - 1;
            if (t >= 1 && v >= v_lo && v < v_hi) {
                float2 pr = ring[(t - 1) & 7];
                *reinterpret_cast<float2*>(dst2 + v * ROWSTR) =
                    make_float2(pr.x + cur.x, pr.y + cur.y);
            }
            int e = xr - 4;
            if (t >= 7 && e >= e_lo && e < e_hi) {
                float sx = 0.f, sy = 0.f;
                #pragma unroll
                for (int k = 0; k < 8; k++) { sx += ring[k].x; sy += ring[k].y; }
                *reinterpret_cast<float2*>(dst8 + (e - 3) * ROWSTR) = make_float2(sx, sy);
            }
        }
    }
    __syncthreads();

    float alpha[TW];
    #pragma unroll
    for (int j = 0; j < TW; j++) alpha[j] = 0.f;

    const int ch  = tid & 7;
    const int row = tid >> 3;        // 0..31
    const int R   = 7 + row;
    const float c0 = g_coef[0], c1 = g_coef[1], c2 = g_coef[2], c3 = g_coef[3];

    // ---- phase 2: all four scans (single barrier kernel) ----
    scanR<0, 1>(V2 + R * ROWSTR + ch, c0, alpha);
    scanP<1, 2>(V2 + (R - 1) * ROWSTR + ch, V2 + (R + 1) * ROWSTR + ch, c1, alpha);
    scanR<3, 4>(V8 + (R - 3) * ROWSTR + ch, c2, alpha);
    scanP<7, 8>(V8 + (R - 7) * ROWSTR + ch, V8 + (R + 1) * ROWSTR + ch, c3, alpha);

    // ---- per-pixel epilogue: BN -> soft histogram -> sigmoid -> add x ----
    const int gcc = gc + ch;
    float AN[8], W8[8];
    #pragma unroll
    for (int k = 0; k < 8; k++) {
        AN[k] = __ldg(anchors + gcc * 8 + k);
        W8[k] = __ldg(widths  + gcc * 8 + k);
    }
    const float bnS = g_bnS[gcc], bnT = g_bnT[gcc];
    const int gh = h0 + row;
    const size_t base = planeB + ((size_t)gh * WW + w0) * NCH + gcc;

    #pragma unroll
    for (int j = 0; j < TW; j++) {
        float a = fmaf(alpha[j], bnS, bnT);
        float t = 0.f;
        #pragma unroll
        for (int k = 0; k < 8; k++) {
            float d = fabsf(a - AN[k]);
            t += fmaxf(fmaf(-W8[k], d, 1.0f), 0.0f);
        }
        float sig = __fdividef(1.0f, 1.0f + __expf(-t));
        out[base + (size_t)j * NCH] = __ldg(x + base + (size_t)j * NCH) + sig;
    }
}

// ---------------- launch ----------------
extern "C" void kernel_launch(void* const* d_in, const int* in_sizes, int n_in,
                              void* d_out, int out_size) {
    const float* x       = (const float*)d_in[0];
    const float* ols     = (const float*)d_in[1];
    const float* anchors = (const float*)d_in[2];
    const float* widths  = (const float*)d_in[3];
    const float* gamma   = (const float*)d_in[4];
    const float* beta    = (const float*)d_in[5];
    const float* mean    = (const float*)d_in[6];
    const float* var     = (const float*)d_in[7];
    float* out = (float*)d_out;

    cudaFuncSetAttribute(mainK, cudaFuncAttributeMaxDynamicSharedMemorySize, SMEM_BYTES);

    initK<<<1, 32>>>();
    minmaxK<<<dim3(128, BB), 256>>>(x);
    finK<<<1, 64>>>(ols, gamma, beta, mean, var);
    mainK<<<dim3((WW / TW) * (HH / TH), 8, BB), 256, SMEM_BYTES>>>(x, anchors, widths, out);
}

// round 6
// speedup vs baseline: 2.0992x; 1.0410x over previous
#include <cuda_runtime.h>

#define HH 224
#define WW 224
#define NCH 64
#define BB 4

#define TH 32
#define TW 16
#define FC 31            // TW + 15 halo cols
#define ROWSTR 248       // 31*8 floats; 4-row x 8-ch warps hit all 32 banks
#define V2R 34           // V2 rows 6..39  stored at (r-6)
#define V8R 32           // V8 rows 7..38  stored at (r-7)
#define V16R 32          // V16c rows 7..38 stored at (r-7)
#define SMEM_BYTES ((V2R + V8R + V16R) * ROWSTR * 4)

#define NPART 128        // minmax partial blocks per batch

// ---------------- device globals (scratch; no allocation) ----------------
__device__ float g_pmn[BB * NPART];
__device__ float g_pmx[BB * NPART];
__device__ float g_sA[BB];      // 1/(max-min+eps)
__device__ float g_xmin[BB];
__device__ float g_coef[4];     // OLS coefficients c_s
__device__ float g_bnS[NCH];    // folded BN scale
__device__ float g_bnT[NCH];    // folded BN bias

// ---------------- kernel 1: per-sample min/max partials ----------------
__global__ void minmaxK(const float* __restrict__ x) {
    const int b = blockIdx.y;
    const int n4 = HH * WW * NCH / 4;
    const float4* xv = reinterpret_cast<const float4*>(x) + (size_t)b * n4;

    float mn = 3.402823466e38f, mx = -3.402823466e38f;
    for (int i = blockIdx.x * blockDim.x + threadIdx.x; i < n4; i += gridDim.x * blockDim.x) {
        float4 v = __ldg(xv + i);
        mn = fminf(mn, fminf(fminf(v.x, v.y), fminf(v.z, v.w)));
        mx = fmaxf(mx, fmaxf(fmaxf(v.x, v.y), fmaxf(v.z, v.w)));
    }
    #pragma unroll
    for (int o = 16; o; o >>= 1) {
        mn = fminf(mn, __shfl_xor_sync(0xffffffffu, mn, o));
        mx = fmaxf(mx, __shfl_xor_sync(0xffffffffu, mx, o));
    }
    __shared__ float smn[8], smx[8];
    int lane = threadIdx.x & 31, wid = threadIdx.x >> 5;
    if (lane == 0) { smn[wid] = mn; smx[wid] = mx; }
    __syncthreads();
    if (wid == 0) {
        mn = smn[lane & 7]; mx = smx[lane & 7];
        #pragma unroll
        for (int o = 4; o; o >>= 1) {
            mn = fminf(mn, __shfl_xor_sync(0xffffffffu, mn, o));
            mx = fmaxf(mx, __shfl_xor_sync(0xffffffffu, mx, o));
        }
        if (lane == 0) {
            g_pmn[b * NPART + blockIdx.x] = mn;
            g_pmx[b * NPART + blockIdx.x] = mx;
        }
    }
}

// ---------------- kernel 2: finalize constants (128 threads) ----------------
__global__ void finK(const float* __restrict__ ols,
                     const float* __restrict__ gamma, const float* __restrict__ beta,
                     const float* __restrict__ mean,  const float* __restrict__ var) {
    int t = threadIdx.x;
    int lane = t & 31, w = t >> 5;      // warp w reduces batch w
    {
        float mn = 3.402823466e38f, mx = -3.402823466e38f;
        #pragma unroll
        for (int k = 0; k < NPART / 32; k++) {
            mn = fminf(mn, g_pmn[w * NPART + k * 32 + lane]);
            mx = fmaxf(mx, g_pmx[w * NPART + k * 32 + lane]);
        }
        #pragma unroll
        for (int o = 16; o; o >>= 1) {
            mn = fminf(mn, __shfl_xor_sync(0xffffffffu, mn, o));
            mx = fmaxf(mx, __shfl_xor_sync(0xffffffffu, mx, o));
        }
        if (lane == 0) {
            g_xmin[w] = mn;
            g_sA[w]   = 1.0f / (mx - mn + 1e-6f);
        }
    }
    if (t < NCH) {
        float s = gamma[t] * rsqrtf(var[t] + 1e-3f);
        g_bnS[t] = s;
        g_bnT[t] = beta[t] - mean[t] * s;
    }
    if (t == 0) {
        const float L2 = 0.69314718055994530942f;
        float wv[4], lr[4];
        float wsum = 0.f, wlr = 0.f;
        #pragma unroll
        for (int s = 0; s < 4; s++) {
            wv[s] = ols[s];
            lr[s] = (float)(s + 1) * L2;
            wsum += wv[s];
            wlr  += wv[s] * lr[s];
        }
        float lrbar = wlr / wsum;
        float den = 0.f;
        #pragma unroll
        for (int s = 0; s < 4; s++) {
            float dx = lr[s] - lrbar;
            den += wv[s] * dx * dx;
        }
        #pragma unroll
        for (int s = 0; s < 4; s++) g_coef[s] = wv[s] * (lr[s] - lrbar) / den;
    }
}

// ---------------- register-ring sliding-window scan, single row ----------------
template <int LO, int HI>
__device__ __forceinline__ void scanR(const float* __restrict__ p,
                                      float coef, float* __restrict__ alpha) {
    constexpr int W = LO + HI + 1;
    float ring[W];
    float ws = 0.f;
    #pragma unroll
    for (int k = 0; k < W; k++) { ring[k] = p[(7 - LO + k) * 8]; ws += ring[k]; }
    #pragma unroll
    for (int j = 0; j < TW; j++) {
        alpha[j] += coef * __logf(ws + 1e-6f);
        if (j < TW - 1) {
            float nv = p[(8 + j + HI) * 8];
            ws += nv - ring[j % W];
            ring[j % W] = nv;
        }
    }
}

// dual-row variant: values are pa[col] + pb[col]
template <int LO, int HI>
__device__ __forceinline__ void scanP(const float* __restrict__ pa,
                                      const float* __restrict__ pb,
                                      float coef, float* __restrict__ alpha) {
    constexpr int W = LO + HI + 1;
    float ring[W];
    float ws = 0.f;
    #pragma unroll
    for (int k = 0; k < W; k++) {
        ring[k] = pa[(7 - LO + k) * 8] + pb[(7 - LO + k) * 8];
        ws += ring[k];
    }
    #pragma unroll
    for (int j = 0; j < TW; j++) {
        alpha[j] += coef * __logf(ws + 1e-6f);
        if (j < TW - 1) {
            float nv = pa[(8 + j + HI) * 8] + pb[(8 + j + HI) * 8];
            ws += nv - ring[j % W];
            ring[j % W] = nv;
        }
    }
}

// ---------------- kernel 3: fused main ----------------
__global__ void __launch_bounds__(256, 2)
mainK(const float* __restrict__ x, const float* __restrict__ anchors,
      const float* __restrict__ widths, float* __restrict__ out) {
    extern __shared__ float sm[];
    float* V2  = sm;                         // rows 6..39 at (r-6)
    float* V8  = sm + V2R * ROWSTR;          // rows 7..38 at (r-7)
    float* V16 = sm + (V2R + V8R) * ROWSTR;  // rows 7..38 at (r-7)

    const int tid = threadIdx.x;
    const int b  = blockIdx.z;
    const int cg = blockIdx.y;           // channel group of 8
    const int tx = blockIdx.x % (WW / TW), ty = blockIdx.x / (WW / TW);
    const int h0 = ty * TH, w0 = tx * TW;
    const int gc = cg * 8;

    const float sA = g_sA[b];
    const float xmsA = -g_xmin[b] * sA;       // xs = x*sA + xmsA
    const size_t planeB = (size_t)b * HH * WW * NCH;

    // ---- phase 1: column walkers emit V2, V8, V16c via sliding sums ----
    // 2 halves x 124 float2 col-slots; each walks 31 xs rows.
    {
        const int half = tid >> 7;            // 0 or 1
        const int slot = tid & 127;           // 0..127; <124 active
        if (slot < 124) {
            const int base = half ? 16 : 0;   // first xs tile-row walked
            const int off2  = half ? (15 - 6) : (-1 - 6);   // v2 store row = t + off2
            const int off8  = half ? (12 - 7) : (-4 - 7);
            const int off16 = half ? (8 - 7)  : (-8 - 7);
            const int tlo2 = half ? 8 : 7, thi2 = half ? 24 : 23;
            const int c = slot >> 2;          // spatial col 0..30
            const int q = slot & 3;           // float2 within 8-ch group
            const int gw = w0 - 7 + c;
            const bool wok = (unsigned)gw < (unsigned)WW;
            const float* px = x + planeB + (size_t)gw * NCH + gc + q * 2;
            float* d2  = V2  + slot * 2;
            float* d8  = V8  + slot * 2;
            float* d16 = V16 + slot * 2;

            float2 xsr[8], v8r[8];
            #pragma unroll
            for (int k = 0; k < 8; k++) {
                xsr[k] = make_float2(0.f, 0.f);
                v8r[k] = make_float2(0.f, 0.f);
            }
            float2 v8s  = make_float2(0.f, 0.f);
            float2 prev = make_float2(0.f, 0.f);

            #pragma unroll
            for (int t = 0; t < 31; t++) {
                int gh = h0 - 7 + base + t;
                float2 cur = make_float2(0.f, 0.f);
                if (wok && (unsigned)gh < (unsigned)HH) {
                    float2 v = *reinterpret_cast<const float2*>(px + (size_t)gh * (WW * NCH));
                    cur = make_float2(fmaf(v.x, sA, xmsA), fmaf(v.y, sA, xmsA));
                }
                // V2[t-1] = xs[t-1] + xs[t]
                if (t >= tlo2 && t <= thi2)
                    *reinterpret_cast<float2*>(d2 + (t + off2) * ROWSTR) =
                        make_float2(prev.x + cur.x, prev.y + cur.y);
                // sliding 8-row sum -> V8[t-4]
                float2 o8 = xsr[t & 7];
                xsr[t & 7] = cur;
                v8s.x += cur.x - o8.x;
                v8s.y += cur.y - o8.y;
                if (t >= 11 && t <= 26)
                    *reinterpret_cast<float2*>(d8 + (t + off8) * ROWSTR) = v8s;
                // V16c[t-8] = V8[t-12] + V8[t-4]
                float2 ov8 = v8r[t & 7];
                v8r[t & 7] = v8s;
                if (t >= 15)
                    *reinterpret_cast<float2*>(d16 + (t + off16) * ROWSTR) =
                        make_float2(ov8.x + v8s.x, ov8.y + v8s.y);
                prev = cur;
            }
        }
    }
    __syncthreads();

    float alpha[TW];
    #pragma unroll
    for (int j = 0; j < TW; j++) alpha[j] = 0.f;

    const int ch  = tid & 7;
    const int row = tid >> 3;        // 0..31
    const int R   = 7 + row;
    const float c0 = g_coef[0], c1 = g_coef[1], c2 = g_coef[2], c3 = g_coef[3];

    // ---- phase 2: four scans (single-barrier kernel) ----
    scanR<0, 1>(V2 + (R - 6) * ROWSTR + ch, c0, alpha);
    scanP<1, 2>(V2 + (R - 7) * ROWSTR + ch, V2 + (R - 5) * ROWSTR + ch, c1, alpha);
    scanR<3, 4>(V8 + (R - 7) * ROWSTR + ch, c2, alpha);
    scanR<7, 8>(V16 + (R - 7) * ROWSTR + ch, c3, alpha);

    // ---- per-pixel epilogue: BN -> soft histogram -> sigmoid -> add x ----
    const int gcc = gc + ch;
    float AN[8], W8[8];
    #pragma unroll
    for (int k = 0; k < 8; k++) {
        AN[k] = __ldg(anchors + gcc * 8 + k);
        W8[k] = __ldg(widths  + gcc * 8 + k);
    }
    const float bnS = g_bnS[gcc], bnT = g_bnT[gcc];
    const int gh = h0 + row;
    const size_t base = planeB + ((size_t)gh * WW + w0) * NCH + gcc;

    #pragma unroll
    for (int j = 0; j < TW; j++) {
        float a = fmaf(alpha[j], bnS, bnT);
        float t = 0.f;
        #pragma unroll
        for (int k = 0; k < 8; k++) {
            float d = fabsf(a - AN[k]);
            t += fmaxf(fmaf(-W8[k], d, 1.0f), 0.0f);
        }
        float sig = __fdividef(1.0f, 1.0f + __expf(-t));
        out[base + (size_t)j * NCH] = __ldg(x + base + (size_t)j * NCH) + sig;
    }
}

// ---------------- launch ----------------
extern "C" void kernel_launch(void* const* d_in, const int* in_sizes, int n_in,
                              void* d_out, int out_size) {
    const float* x       = (const float*)d_in[0];
    const float* ols     = (const float*)d_in[1];
    const float* anchors = (const float*)d_in[2];
    const float* widths  = (const float*)d_in[3];
    const float* gamma   = (const float*)d_in[4];
    const float* beta    = (const float*)d_in[5];
    const float* mean    = (const float*)d_in[6];
    const float* var     = (const float*)d_in[7];
    float* out = (float*)d_out;

    cudaFuncSetAttribute(mainK, cudaFuncAttributeMaxDynamicSharedMemorySize, SMEM_BYTES);

    minmaxK<<<dim3(NPART, BB), 256>>>(x);
    finK<<<1, 128>>>(ols, gamma, beta, mean, var);
    mainK<<<dim3((WW / TW) * (HH / TH), 8, BB), 256, SMEM_BYTES>>>(x, anchors, widths, out);
}